// round 2
// baseline (speedup 1.0000x reference)
#include <cuda_runtime.h>

#define L_EXP 16
#define IN0   7
#define C0    16
#define C1    32
#define C2    16
#define NEG   0.2f

#define TPB_MAIN 128
#define PPT      4                 // points per thread (2 f32x2 pairs)
#define PPB      (TPB_MAIN * PPT)  // 512 points per block, uniform expert

#define PERM_CAP 1200000

__device__ int g_perm[PERM_CAP];
__device__ int g_counts[L_EXP];
__device__ int g_offsets[L_EXP + 1];
__device__ int g_cursor[L_EXP];

// ---------------- packed f32x2 FMA ----------------
union F2U { float2 f; unsigned long long u; };

__device__ __forceinline__ float2 ffma2(float2 a, float2 b, float2 c) {
    F2U ua, ub, uc, ud;
    ua.f = a; ub.f = b; uc.f = c;
    asm("fma.rn.f32x2 %0, %1, %2, %3;" : "=l"(ud.u) : "l"(ua.u), "l"(ub.u), "l"(uc.u));
    return ud.f;
}

__device__ __forceinline__ float2 lrelu2(float2 v) {
    v.x = fmaxf(v.x, NEG * v.x);
    v.y = fmaxf(v.y, NEG * v.y);
    return v;
}

// ---------------- pass 1: fill perm with -1, zero counts, histogram ----------------
__global__ void k_fill_hist(const int* __restrict__ idx, int n, int fill_len)
{
    __shared__ int sh[L_EXP];
    int t = threadIdx.x;
    if (t < L_EXP) sh[t] = 0;
    __syncthreads();

    int gtid = blockIdx.x * blockDim.x + t;
    int stride = gridDim.x * blockDim.x;
    for (int i = gtid; i < fill_len; i += stride) g_perm[i] = -1;
    if (gtid < L_EXP) g_counts[gtid] = 0;
    // histogram needs counts zeroed first -> do local hist, flush later kernel? No:
    // counts zeroing races with other blocks' atomics. Do hist into smem, flush in
    // k_scan-safe way: accumulate into a separate staging? Simpler: zero here only
    // from block 0 is still racy. Instead: histogram into sh, and flush with
    // atomicAdd AFTER a device-wide ordering is impossible intra-kernel.
    // -> counts are zeroed by block-0-thread trick is unsafe; so we zero counts in
    //    this kernel ONLY via gtid<16 above, and do the histogram in the NEXT kernel.
    (void)idx; (void)sh;
}

__global__ void k_hist(const int* __restrict__ idx, int n)
{
    __shared__ int sh[L_EXP];
    int t = threadIdx.x;
    if (t < L_EXP) sh[t] = 0;
    __syncthreads();
    int gtid = blockIdx.x * blockDim.x + t;
    int stride = gridDim.x * blockDim.x;
    for (int i = gtid; i < n; i += stride) atomicAdd(&sh[idx[i]], 1);
    __syncthreads();
    if (t < L_EXP && sh[t] > 0) atomicAdd(&g_counts[t], sh[t]);
}

// ---------------- pass 2: scan (pad each expert segment to PPB) ----------------
__global__ void k_scan()
{
    int off = 0;
    g_offsets[0] = 0;
    for (int e = 0; e < L_EXP; e++) {
        int c  = g_counts[e];
        int pc = ((c + PPB - 1) / PPB) * PPB;
        off += pc;
        g_offsets[e + 1] = off;
        g_cursor[e] = g_offsets[e];
    }
}

// ---------------- pass 3: scatter point ids into expert segments ----------------
__global__ void k_scatter(const int* __restrict__ idx, int n)
{
    __shared__ int scnt[L_EXP];
    __shared__ int sbase[L_EXP];
    int t = threadIdx.x;
    if (t < L_EXP) scnt[t] = 0;
    __syncthreads();

    int p = blockIdx.x * blockDim.x + t;
    int e = -1, r = 0;
    if (p < n) {
        e = idx[p];
        r = atomicAdd(&scnt[e], 1);
    }
    __syncthreads();
    if (t < L_EXP) sbase[t] = (scnt[t] > 0) ? atomicAdd(&g_cursor[t], scnt[t]) : 0;
    __syncthreads();
    if (e >= 0) g_perm[sbase[e] + r] = p;
}

// ---------------- pass 4: uniform-expert MLP ----------------
__global__ __launch_bounds__(TPB_MAIN, 2)
void k_main(const float* __restrict__ x,
            const float* __restrict__ W0, const float* __restrict__ b0,
            const float* __restrict__ W1, const float* __restrict__ b1,
            const float* __restrict__ W2, const float* __restrict__ b2,
            float* __restrict__ out)
{
    // duplicated weights: {w,w} pairs, float4-aligned
    __shared__ __align__(16) float sW0[IN0 * C0 * 2];
    __shared__ __align__(16) float sW1[C0 * C1 * 2];
    __shared__ __align__(16) float sW2[C1 * C2 * 2];
    __shared__ float2 sB0[C0];
    __shared__ float2 sB1[C1];
    __shared__ float2 sB2[C2];
    __shared__ int s_e;

    const int t = threadIdx.x;
    const int base = blockIdx.x * PPB;

    if (t == 0) {
        int e = -1;
        if (base < g_offsets[L_EXP]) {
            for (int k = 0; k < L_EXP; k++)
                if (base >= g_offsets[k] && base < g_offsets[k + 1]) { e = k; break; }
        }
        s_e = e;
    }
    __syncthreads();
    const int e = s_e;
    if (e < 0) return;

    const float* W0e = W0 + e * IN0 * C0;
    const float* W1e = W1 + e * C0 * C1;
    const float* W2e = W2 + e * C1 * C2;
    for (int d = t; d < IN0 * C0; d += TPB_MAIN) { float w = W0e[d]; ((float2*)sW0)[d] = make_float2(w, w); }
    for (int d = t; d < C0 * C1;  d += TPB_MAIN) { float w = W1e[d]; ((float2*)sW1)[d] = make_float2(w, w); }
    for (int d = t; d < C1 * C2;  d += TPB_MAIN) { float w = W2e[d]; ((float2*)sW2)[d] = make_float2(w, w); }
    for (int d = t; d < C0; d += TPB_MAIN) { float w = b0[e * C0 + d]; sB0[d] = make_float2(w, w); }
    for (int d = t; d < C1; d += TPB_MAIN) { float w = b1[e * C1 + d]; sB1[d] = make_float2(w, w); }
    for (int d = t; d < C2; d += TPB_MAIN) { float w = b2[e * C2 + d]; sB2[d] = make_float2(w, w); }
    __syncthreads();

    // 4 points: slots base + t + k*128, paired (0,1) and (2,3)
    int pi[PPT];
    #pragma unroll
    for (int k = 0; k < PPT; k++) pi[k] = g_perm[base + t + k * TPB_MAIN];

    // load x packed into pairs
    float2 h0[2][IN0];
    #pragma unroll
    for (int q = 0; q < 2; q++) {
        const int pa = pi[2 * q], pb = pi[2 * q + 1];
        const float* xa = (pa >= 0) ? (x + (size_t)pa * IN0) : 0;
        const float* xb = (pb >= 0) ? (x + (size_t)pb * IN0) : 0;
        #pragma unroll
        for (int i = 0; i < IN0; i++)
            h0[q][i] = make_float2(xa ? xa[i] : 0.f, xb ? xb[i] : 0.f);
    }

    // ---- layer 0: 7 -> 16 ----
    float2 h1[2][C0];
    #pragma unroll
    for (int o = 0; o < C0; o++) { h1[0][o] = sB0[o]; h1[1][o] = sB0[o]; }
    #pragma unroll
    for (int i = 0; i < IN0; i++) {
        #pragma unroll
        for (int oj = 0; oj < C0 / 2; oj++) {
            float4 w4 = *(const float4*)&sW0[(i * C0 + 2 * oj) * 2];
            float2 wA = make_float2(w4.x, w4.y);
            float2 wB = make_float2(w4.z, w4.w);
            #pragma unroll
            for (int q = 0; q < 2; q++) {
                h1[q][2 * oj]     = ffma2(h0[q][i], wA, h1[q][2 * oj]);
                h1[q][2 * oj + 1] = ffma2(h0[q][i], wB, h1[q][2 * oj + 1]);
            }
        }
    }
    #pragma unroll
    for (int o = 0; o < C0; o++) { h1[0][o] = lrelu2(h1[0][o]); h1[1][o] = lrelu2(h1[1][o]); }

    // ---- layer 1: 16 -> 32 ----
    float2 h2[2][C1];
    #pragma unroll
    for (int o = 0; o < C1; o++) { h2[0][o] = sB1[o]; h2[1][o] = sB1[o]; }
    #pragma unroll 2
    for (int i = 0; i < C0; i++) {
        #pragma unroll
        for (int oj = 0; oj < C1 / 2; oj++) {
            float4 w4 = *(const float4*)&sW1[(i * C1 + 2 * oj) * 2];
            float2 wA = make_float2(w4.x, w4.y);
            float2 wB = make_float2(w4.z, w4.w);
            #pragma unroll
            for (int q = 0; q < 2; q++) {
                h2[q][2 * oj]     = ffma2(h1[q][i], wA, h2[q][2 * oj]);
                h2[q][2 * oj + 1] = ffma2(h1[q][i], wB, h2[q][2 * oj + 1]);
            }
        }
    }
    #pragma unroll
    for (int o = 0; o < C1; o++) { h2[0][o] = lrelu2(h2[0][o]); h2[1][o] = lrelu2(h2[1][o]); }

    // ---- layer 2: 32 -> 16, chunked in halves of 8 outputs ----
    #pragma unroll
    for (int och = 0; och < 2; och++) {
        float2 a2[2][8];
        #pragma unroll
        for (int o = 0; o < 8; o++) { a2[0][o] = sB2[och * 8 + o]; a2[1][o] = sB2[och * 8 + o]; }
        #pragma unroll 4
        for (int i = 0; i < C1; i++) {
            #pragma unroll
            for (int oj = 0; oj < 4; oj++) {
                float4 w4 = *(const float4*)&sW2[(i * C2 + och * 8 + 2 * oj) * 2];
                float2 wA = make_float2(w4.x, w4.y);
                float2 wB = make_float2(w4.z, w4.w);
                #pragma unroll
                for (int q = 0; q < 2; q++) {
                    a2[q][2 * oj]     = ffma2(h2[q][i], wA, a2[q][2 * oj]);
                    a2[q][2 * oj + 1] = ffma2(h2[q][i], wB, a2[q][2 * oj + 1]);
                }
            }
        }
        #pragma unroll
        for (int o = 0; o < 8; o++) { a2[0][o] = lrelu2(a2[0][o]); a2[1][o] = lrelu2(a2[1][o]); }

        #pragma unroll
        for (int q = 0; q < 2; q++) {
            const int pa = pi[2 * q], pb = pi[2 * q + 1];
            if (pa >= 0) {
                float4* op = (float4*)(out + (size_t)pa * C2 + och * 8);
                op[0] = make_float4(a2[q][0].x, a2[q][1].x, a2[q][2].x, a2[q][3].x);
                op[1] = make_float4(a2[q][4].x, a2[q][5].x, a2[q][6].x, a2[q][7].x);
            }
            if (pb >= 0) {
                float4* op = (float4*)(out + (size_t)pb * C2 + och * 8);
                op[0] = make_float4(a2[q][0].y, a2[q][1].y, a2[q][2].y, a2[q][3].y);
                op[1] = make_float4(a2[q][4].y, a2[q][5].y, a2[q][6].y, a2[q][7].y);
            }
        }
    }
}

extern "C" void kernel_launch(void* const* d_in, const int* in_sizes, int n_in,
                              void* d_out, int out_size)
{
    const float* x   = (const float*)d_in[0];
    const int*   idx = (const int*)  d_in[1];
    const float* W0  = (const float*)d_in[2];
    const float* b0  = (const float*)d_in[3];
    const float* W1  = (const float*)d_in[4];
    const float* b1  = (const float*)d_in[5];
    const float* W2  = (const float*)d_in[6];
    const float* b2  = (const float*)d_in[7];
    float* out = (float*)d_out;

    const int n = in_sizes[1];

    int grid_main = (n + L_EXP * (PPB - 1) + (PPB - 1)) / PPB;
    int fill_len  = grid_main * PPB;
    if (fill_len > PERM_CAP) fill_len = PERM_CAP;

    k_fill_hist<<<592, 256>>>(idx, n, fill_len);
    k_hist<<<592, 256>>>(idx, n);
    k_scan<<<1, 1>>>();
    k_scatter<<<(n + 255) / 256, 256>>>(idx, n);
    k_main<<<grid_main, TPB_MAIN>>>(x, W0, b0, W1, b1, W2, b2, out);
}

// round 3
// speedup vs baseline: 1.3866x; 1.3866x over previous
#include <cuda_runtime.h>

#define L_EXP 16
#define IN0   7
#define C0    16
#define C1    32
#define C2    16
#define NEG   0.2f

// Quad-interleaved layouts: sW[((i*OQ + oq)*16 + e)*4 + k]
// -> one LDS.128 per (i, output-quad), conflict-free for arbitrary expert mixes.
#define W0T_SZ (IN0 * C0 * L_EXP)   // 1792  (i<7,  oq<4)
#define B0T_SZ (C0 * L_EXP)         // 256   (oq<4)
#define W1T_SZ (C0 * C1 * L_EXP)    // 8192  (i<16, oq<8)
#define B1T_SZ (C1 * L_EXP)         // 512   (oq<8)
#define W2T_SZ (C1 * C2 * L_EXP)    // 8192  (i<32, oq<4)
#define B2T_SZ (C2 * L_EXP)         // 256   (oq<4)
#define SM_FLOATS (W0T_SZ + B0T_SZ + W1T_SZ + B1T_SZ + W2T_SZ + B2T_SZ) // 19200
#define SM_BYTES  (SM_FLOATS * 4)   // 76800

#define TPB 256
#define PPT 2
#define PPB (TPB * PPT)

__global__ __launch_bounds__(TPB)
void wnet_kernel(const float* __restrict__ x,
                 const int*   __restrict__ idx,
                 const float* __restrict__ W0, const float* __restrict__ b0,
                 const float* __restrict__ W1, const float* __restrict__ b1,
                 const float* __restrict__ W2, const float* __restrict__ b2,
                 float* __restrict__ out, int n)
{
    extern __shared__ __align__(16) float sm[];
    float* sW0 = sm;
    float* sB0 = sW0 + W0T_SZ;
    float* sW1 = sB0 + B0T_SZ;
    float* sB1 = sW1 + W1T_SZ;
    float* sW2 = sB1 + B1T_SZ;
    float* sB2 = sW2 + W2T_SZ;

    const int t = threadIdx.x;

    // ---- Stage weights, transposed to quad-expert-interleaved ----
    // sW0 idx = i*256 + oq*64 + e*4 + k  <-  W0[(e*7+i)*16 + 4*oq + k]
    for (int d = t; d < W0T_SZ; d += TPB) {
        int k = d & 3, e = (d >> 2) & 15, oq = (d >> 6) & 3, i = d >> 8;
        sW0[d] = W0[(e * IN0 + i) * C0 + 4 * oq + k];
    }
    for (int d = t; d < B0T_SZ; d += TPB) {
        int k = d & 3, e = (d >> 2) & 15, oq = d >> 6;
        sB0[d] = b0[e * C0 + 4 * oq + k];
    }
    // sW1 idx = i*512 + oq*64 + e*4 + k  <-  W1[(e*16+i)*32 + 4*oq + k]
    for (int d = t; d < W1T_SZ; d += TPB) {
        int k = d & 3, e = (d >> 2) & 15, oq = (d >> 6) & 7, i = d >> 9;
        sW1[d] = W1[(e * C0 + i) * C1 + 4 * oq + k];
    }
    for (int d = t; d < B1T_SZ; d += TPB) {
        int k = d & 3, e = (d >> 2) & 15, oq = d >> 6;
        sB1[d] = b1[e * C1 + 4 * oq + k];
    }
    // sW2 idx = i*256 + oq*64 + e*4 + k  <-  W2[(e*32+i)*16 + 4*oq + k]
    for (int d = t; d < W2T_SZ; d += TPB) {
        int k = d & 3, e = (d >> 2) & 15, oq = (d >> 6) & 3, i = d >> 8;
        sW2[d] = W2[(e * C1 + i) * C2 + 4 * oq + k];
    }
    for (int d = t; d < B2T_SZ; d += TPB) {
        int k = d & 3, e = (d >> 2) & 15, oq = d >> 6;
        sB2[d] = b2[e * C2 + 4 * oq + k];
    }
    __syncthreads();

    const int base = blockIdx.x * PPB + t;

    #pragma unroll
    for (int rep = 0; rep < PPT; rep++) {
        const int p = base + rep * TPB;
        if (p < n) {
            const int e4 = idx[p] * 4;
            const float* xp = x + (size_t)p * IN0;

            float h0[IN0];
            #pragma unroll
            for (int i = 0; i < IN0; i++) h0[i] = xp[i];

            // ---- Layer 0: 7 -> 16 ----
            float h1[C0];
            #pragma unroll
            for (int oq = 0; oq < 4; oq++) {
                float4 b = *(const float4*)&sB0[oq * 64 + e4];
                h1[4*oq+0] = b.x; h1[4*oq+1] = b.y; h1[4*oq+2] = b.z; h1[4*oq+3] = b.w;
            }
            #pragma unroll
            for (int i = 0; i < IN0; i++) {
                const float hv = h0[i];
                #pragma unroll
                for (int oq = 0; oq < 4; oq++) {
                    float4 w = *(const float4*)&sW0[i * 256 + oq * 64 + e4];
                    h1[4*oq+0] = fmaf(hv, w.x, h1[4*oq+0]);
                    h1[4*oq+1] = fmaf(hv, w.y, h1[4*oq+1]);
                    h1[4*oq+2] = fmaf(hv, w.z, h1[4*oq+2]);
                    h1[4*oq+3] = fmaf(hv, w.w, h1[4*oq+3]);
                }
            }
            #pragma unroll
            for (int o = 0; o < C0; o++) h1[o] = fmaxf(h1[o], NEG * h1[o]);

            // ---- Layer 1: 16 -> 32 ----
            float h2[C1];
            #pragma unroll
            for (int oq = 0; oq < 8; oq++) {
                float4 b = *(const float4*)&sB1[oq * 64 + e4];
                h2[4*oq+0] = b.x; h2[4*oq+1] = b.y; h2[4*oq+2] = b.z; h2[4*oq+3] = b.w;
            }
            #pragma unroll
            for (int i = 0; i < C0; i++) {
                const float hv = h1[i];
                #pragma unroll
                for (int oq = 0; oq < 8; oq++) {
                    float4 w = *(const float4*)&sW1[i * 512 + oq * 64 + e4];
                    h2[4*oq+0] = fmaf(hv, w.x, h2[4*oq+0]);
                    h2[4*oq+1] = fmaf(hv, w.y, h2[4*oq+1]);
                    h2[4*oq+2] = fmaf(hv, w.z, h2[4*oq+2]);
                    h2[4*oq+3] = fmaf(hv, w.w, h2[4*oq+3]);
                }
            }
            #pragma unroll
            for (int o = 0; o < C1; o++) h2[o] = fmaxf(h2[o], NEG * h2[o]);

            // ---- Layer 2: 32 -> 16 ----
            float ho[C2];
            #pragma unroll
            for (int oq = 0; oq < 4; oq++) {
                float4 b = *(const float4*)&sB2[oq * 64 + e4];
                ho[4*oq+0] = b.x; ho[4*oq+1] = b.y; ho[4*oq+2] = b.z; ho[4*oq+3] = b.w;
            }
            #pragma unroll
            for (int i = 0; i < C1; i++) {
                const float hv = h2[i];
                #pragma unroll
                for (int oq = 0; oq < 4; oq++) {
                    float4 w = *(const float4*)&sW2[i * 256 + oq * 64 + e4];
                    ho[4*oq+0] = fmaf(hv, w.x, ho[4*oq+0]);
                    ho[4*oq+1] = fmaf(hv, w.y, ho[4*oq+1]);
                    ho[4*oq+2] = fmaf(hv, w.z, ho[4*oq+2]);
                    ho[4*oq+3] = fmaf(hv, w.w, ho[4*oq+3]);
                }
            }
            #pragma unroll
            for (int o = 0; o < C2; o++) ho[o] = fmaxf(ho[o], NEG * ho[o]);

            float4* op = reinterpret_cast<float4*>(out + (size_t)p * C2);
            op[0] = make_float4(ho[0],  ho[1],  ho[2],  ho[3]);
            op[1] = make_float4(ho[4],  ho[5],  ho[6],  ho[7]);
            op[2] = make_float4(ho[8],  ho[9],  ho[10], ho[11]);
            op[3] = make_float4(ho[12], ho[13], ho[14], ho[15]);
        }
    }
}

extern "C" void kernel_launch(void* const* d_in, const int* in_sizes, int n_in,
                              void* d_out, int out_size)
{
    const float* x   = (const float*)d_in[0];
    const int*   idx = (const int*)  d_in[1];
    const float* W0  = (const float*)d_in[2];
    const float* b0  = (const float*)d_in[3];
    const float* W1  = (const float*)d_in[4];
    const float* b1  = (const float*)d_in[5];
    const float* W2  = (const float*)d_in[6];
    const float* b2  = (const float*)d_in[7];
    float* out = (float*)d_out;

    const int n = in_sizes[1];

    cudaFuncSetAttribute(wnet_kernel,
                         cudaFuncAttributeMaxDynamicSharedMemorySize, SM_BYTES);

    const int grid = (n + PPB - 1) / PPB;
    wnet_kernel<<<grid, TPB, SM_BYTES>>>(x, idx, W0, b0, W1, b1, W2, b2, out, n);
}

// round 5
// speedup vs baseline: 3.3796x; 2.4373x over previous
#include <cuda_runtime.h>
#include <stdint.h>

#define L_EXP 16
#define IN0   7
#define C0    16
#define C1    32
#define C2    16
#define NEG   0.2f
#define TPB   256

#define PERM_CAP 1100000

__device__ int g_counts[L_EXP];
__device__ int g_offsets[L_EXP + 1];
__device__ int g_cursor[L_EXP];
__device__ int g_perm[PERM_CAP];

// ---------------- packed f32x2 FMA ----------------
union F2U { float2 f; unsigned long long u; };

__device__ __forceinline__ float2 ffma2(float2 a, float2 b, float2 c) {
    F2U ua, ub, uc, ud;
    ua.f = a; ub.f = b; uc.f = c;
    asm("fma.rn.f32x2 %0, %1, %2, %3;" : "=l"(ud.u) : "l"(ua.u), "l"(ub.u), "l"(uc.u));
    return ud.f;
}

__device__ __forceinline__ float lrelu(float v) { return fmaxf(v, NEG * v); }

// ---------------- pass 1: zero counts ----------------
__global__ void k_zero() {
    if (threadIdx.x < L_EXP) g_counts[threadIdx.x] = 0;
}

// ---------------- pass 2: histogram ----------------
__global__ void k_hist(const int* __restrict__ idx, int n) {
    __shared__ int sh[L_EXP];
    int t = threadIdx.x;
    if (t < L_EXP) sh[t] = 0;
    __syncthreads();
    int gtid = blockIdx.x * blockDim.x + t;
    int stride = gridDim.x * blockDim.x;
    if ((((uintptr_t)idx) & 15) == 0) {
        int n4 = n >> 2;
        const int4* idx4 = (const int4*)idx;
        for (int i = gtid; i < n4; i += stride) {
            int4 v = idx4[i];
            atomicAdd(&sh[v.x], 1); atomicAdd(&sh[v.y], 1);
            atomicAdd(&sh[v.z], 1); atomicAdd(&sh[v.w], 1);
        }
        for (int i = 4 * n4 + gtid; i < n; i += stride) atomicAdd(&sh[idx[i]], 1);
    } else {
        for (int i = gtid; i < n; i += stride) atomicAdd(&sh[idx[i]], 1);
    }
    __syncthreads();
    if (t < L_EXP && sh[t] > 0) atomicAdd(&g_counts[t], sh[t]);
}

// ---------------- pass 3: scan + fill only pad slots with -1 ----------------
__global__ void k_scan_pad() {
    int t = threadIdx.x;
    if (t == 0) {
        int off = 0;
        g_offsets[0] = 0;
        for (int e = 0; e < L_EXP; e++) {
            int c = g_counts[e];
            g_cursor[e] = off;
            off += ((c + TPB - 1) / TPB) * TPB;
            g_offsets[e + 1] = off;
        }
    }
    __syncthreads();
    for (int e = 0; e < L_EXP; e++) {
        int s = g_offsets[e] + g_counts[e];
        int en = g_offsets[e + 1];
        for (int i = s + t; i < en; i += blockDim.x) g_perm[i] = -1;
    }
}

// ---------------- pass 4: scatter point ids into expert segments ----------------
__global__ void k_scatter(const int* __restrict__ idx, int n) {
    __shared__ int scnt[L_EXP];
    __shared__ int sbase[L_EXP];
    int t = threadIdx.x;
    if (t < L_EXP) scnt[t] = 0;
    __syncthreads();
    int p = blockIdx.x * blockDim.x + t;
    int e = -1, r = 0;
    if (p < n) {
        e = idx[p];
        r = atomicAdd(&scnt[e], 1);
    }
    __syncthreads();
    if (t < L_EXP) sbase[t] = (scnt[t] > 0) ? atomicAdd(&g_cursor[t], scnt[t]) : 0;
    __syncthreads();
    if (e >= 0) g_perm[sbase[e] + r] = p;
}

// ---------------- pass 5: block-uniform-expert MLP ----------------
__global__ __launch_bounds__(TPB)
void k_main(const float* __restrict__ x,
            const float* __restrict__ W0, const float* __restrict__ b0,
            const float* __restrict__ W1, const float* __restrict__ b1,
            const float* __restrict__ W2, const float* __restrict__ b2,
            float* __restrict__ out)
{
    __shared__ __align__(16) float sW0[IN0 * C0];
    __shared__ __align__(16) float sW1[C0 * C1];
    __shared__ __align__(16) float sW2[C1 * C2];
    __shared__ __align__(16) float sB0[C0];
    __shared__ __align__(16) float sB1[C1];
    __shared__ __align__(16) float sB2[C2];
    __shared__ int s_e;

    const int t = threadIdx.x;
    const int base = blockIdx.x * TPB;

    if (t == 0) {
        int e = -1;
        if (base < g_offsets[L_EXP]) {
            int acc = 0;
            #pragma unroll
            for (int k = L_EXP; k >= 1; k--)
                acc = (base < g_offsets[k]) ? (k - 1) : acc;
            e = acc;
        }
        s_e = e;
    }
    __syncthreads();
    const int e = s_e;
    if (e < 0) return;

    // stage this expert's weights (tiny: 1200 floats)
    const float* W0e = W0 + e * IN0 * C0;
    const float* W1e = W1 + e * C0 * C1;
    const float* W2e = W2 + e * C1 * C2;
    for (int d = t; d < IN0 * C0; d += TPB) sW0[d] = W0e[d];
    for (int d = t; d < C0 * C1;  d += TPB) sW1[d] = W1e[d];
    for (int d = t; d < C1 * C2;  d += TPB) sW2[d] = W2e[d];
    if (t < C0) sB0[t] = b0[e * C0 + t];
    if (t < C1) sB1[t] = b1[e * C1 + t];
    if (t < C2) sB2[t] = b2[e * C2 + t];
    __syncthreads();

    const int p = g_perm[base + t];

    float h0[IN0];
    #pragma unroll
    for (int i = 0; i < IN0; i++) h0[i] = 0.f;
    if (p >= 0) {
        const float* xp = x + (size_t)p * IN0;
        #pragma unroll
        for (int i = 0; i < IN0; i++) h0[i] = __ldg(xp + i);
    }

    // ---- layer 0: 7 -> 16 (float2 accumulators over output pairs) ----
    float2 a0[C0 / 2];
    #pragma unroll
    for (int q = 0; q < C0 / 2; q++) a0[q] = ((const float2*)sB0)[q];
    #pragma unroll
    for (int i = 0; i < IN0; i++) {
        const float2 hd = make_float2(h0[i], h0[i]);
        #pragma unroll
        for (int q4 = 0; q4 < C0 / 4; q4++) {
            float4 w = *(const float4*)&sW0[i * C0 + 4 * q4];
            a0[2 * q4]     = ffma2(hd, make_float2(w.x, w.y), a0[2 * q4]);
            a0[2 * q4 + 1] = ffma2(hd, make_float2(w.z, w.w), a0[2 * q4 + 1]);
        }
    }
    float h1[C0];
    #pragma unroll
    for (int q = 0; q < C0 / 2; q++) {
        h1[2 * q]     = lrelu(a0[q].x);
        h1[2 * q + 1] = lrelu(a0[q].y);
    }

    // ---- layer 1: 16 -> 32 ----
    float2 a1[C1 / 2];
    #pragma unroll
    for (int q = 0; q < C1 / 2; q++) a1[q] = ((const float2*)sB1)[q];
    #pragma unroll
    for (int i = 0; i < C0; i++) {
        const float2 hd = make_float2(h1[i], h1[i]);
        #pragma unroll
        for (int q4 = 0; q4 < C1 / 4; q4++) {
            float4 w = *(const float4*)&sW1[i * C1 + 4 * q4];
            a1[2 * q4]     = ffma2(hd, make_float2(w.x, w.y), a1[2 * q4]);
            a1[2 * q4 + 1] = ffma2(hd, make_float2(w.z, w.w), a1[2 * q4 + 1]);
        }
    }
    float h2[C1];
    #pragma unroll
    for (int q = 0; q < C1 / 2; q++) {
        h2[2 * q]     = lrelu(a1[q].x);
        h2[2 * q + 1] = lrelu(a1[q].y);
    }

    // ---- layer 2: 32 -> 16 ----
    float2 a2[C2 / 2];
    #pragma unroll
    for (int q = 0; q < C2 / 2; q++) a2[q] = ((const float2*)sB2)[q];
    #pragma unroll
    for (int i = 0; i < C1; i++) {
        const float2 hd = make_float2(h2[i], h2[i]);
        #pragma unroll
        for (int q4 = 0; q4 < C2 / 4; q4++) {
            float4 w = *(const float4*)&sW2[i * C2 + 4 * q4];
            a2[2 * q4]     = ffma2(hd, make_float2(w.x, w.y), a2[2 * q4]);
            a2[2 * q4 + 1] = ffma2(hd, make_float2(w.z, w.w), a2[2 * q4 + 1]);
        }
    }

    if (p >= 0) {
        float ho[C2];
        #pragma unroll
        for (int q = 0; q < C2 / 2; q++) {
            ho[2 * q]     = lrelu(a2[q].x);
            ho[2 * q + 1] = lrelu(a2[q].y);
        }
        float4* op = reinterpret_cast<float4*>(out + (size_t)p * C2);
        op[0] = make_float4(ho[0],  ho[1],  ho[2],  ho[3]);
        op[1] = make_float4(ho[4],  ho[5],  ho[6],  ho[7]);
        op[2] = make_float4(ho[8],  ho[9],  ho[10], ho[11]);
        op[3] = make_float4(ho[12], ho[13], ho[14], ho[15]);
    }
}

extern "C" void kernel_launch(void* const* d_in, const int* in_sizes, int n_in,
                              void* d_out, int out_size)
{
    const float* x   = (const float*)d_in[0];
    const int*   idx = (const int*)  d_in[1];
    const float* W0  = (const float*)d_in[2];
    const float* b0  = (const float*)d_in[3];
    const float* W1  = (const float*)d_in[4];
    const float* b1  = (const float*)d_in[5];
    const float* W2  = (const float*)d_in[6];
    const float* b2  = (const float*)d_in[7];
    float* out = (float*)d_out;

    const int n = in_sizes[1];

    k_zero<<<1, 32>>>();
    k_hist<<<296, 256>>>(idx, n);
    k_scan_pad<<<1, 256>>>();
    k_scatter<<<(n + 255) / 256, 256>>>(idx, n);

    const int grid_main = (n + L_EXP * (TPB - 1) + TPB - 1) / TPB;
    k_main<<<grid_main, TPB>>>(x, W0, b0, W1, b1, W2, b2, out);
}

// round 6
// speedup vs baseline: 4.1687x; 1.2335x over previous
#include <cuda_runtime.h>
#include <stdint.h>

#define L_EXP 16
#define IN0   7
#define C0    16
#define C1    32
#define C2    16
#define NEG   0.2f
#define TPB   256
#define PPT   2
#define PPB   (TPB * PPT)        // 512

#define SEG_SHIFT 16
#define SEG       (1 << SEG_SHIFT)          // 65536 slots per expert
#define BLKS_PER_SEG (SEG / PPB)            // 128
#define GRID_MAIN (L_EXP * BLKS_PER_SEG)    // 2048

__device__ int    g_cursor[L_EXP];
__device__ int    g_perm[L_EXP * SEG];          // 4 MB
__device__ float4 g_xb[L_EXP * SEG * 2];        // 32 MB, 2 float4 per slot

// ---------------- packed f32x2 FMA ----------------
union F2U { float2 f; unsigned long long u; };
__device__ __forceinline__ float2 ffma2(float2 a, float2 b, float2 c) {
    F2U ua, ub, uc, ud;
    ua.f = a; ub.f = b; uc.f = c;
    asm("fma.rn.f32x2 %0, %1, %2, %3;" : "=l"(ud.u) : "l"(ua.u), "l"(ub.u), "l"(uc.u));
    return ud.f;
}
__device__ __forceinline__ float lrelu(float v) { return fmaxf(v, NEG * v); }

// ---------------- pass 1: reset segment cursors ----------------
__global__ void k_init() {
    if (threadIdx.x < L_EXP) g_cursor[threadIdx.x] = threadIdx.x << SEG_SHIFT;
}

// ---------------- pass 2: single-pass bin + x copy ----------------
__global__ void k_scatter(const int* __restrict__ idx,
                          const float* __restrict__ x, int n) {
    __shared__ int scnt[L_EXP];
    __shared__ int sbase[L_EXP];
    const int t = threadIdx.x;
    if (t < L_EXP) scnt[t] = 0;
    __syncthreads();

    const int p = blockIdx.x * TPB + t;
    int e = -1, r = 0;
    if (p < n) {
        e = idx[p];
        r = atomicAdd(&scnt[e], 1);
    }
    __syncthreads();
    if (t < L_EXP) sbase[t] = (scnt[t] > 0) ? atomicAdd(&g_cursor[t], scnt[t]) : 0;
    __syncthreads();

    if (e >= 0) {
        const int slot = sbase[e] + r;
        if (slot < ((e + 1) << SEG_SHIFT)) {   // statistical impossibility guard
            g_perm[slot] = p;
            const float* xp = x + (size_t)p * IN0;
            g_xb[2 * slot]     = make_float4(xp[0], xp[1], xp[2], xp[3]);
            g_xb[2 * slot + 1] = make_float4(xp[4], xp[5], xp[6], 0.f);
        }
    }
}

// ---------------- pass 3: block-uniform-expert MLP, 2 pts/thread ----------------
__global__ __launch_bounds__(TPB)
void k_main(const float* __restrict__ W0, const float* __restrict__ b0,
            const float* __restrict__ W1, const float* __restrict__ b1,
            const float* __restrict__ W2, const float* __restrict__ b2,
            float* __restrict__ out)
{
    __shared__ __align__(16) float sW0[IN0 * C0];
    __shared__ __align__(16) float sW1[C0 * C1];
    __shared__ __align__(16) float sW2[C1 * C2];
    __shared__ __align__(16) float sB0[C0];
    __shared__ __align__(16) float sB1[C1];
    __shared__ __align__(16) float sB2[C2];

    const int e          = blockIdx.x >> 7;                 // / BLKS_PER_SEG
    const int local_base = (blockIdx.x & (BLKS_PER_SEG - 1)) * PPB;
    const int cnt        = g_cursor[e] - (e << SEG_SHIFT);
    if (local_base >= cnt) return;

    const int t = threadIdx.x;

    const float* W0e = W0 + e * IN0 * C0;
    const float* W1e = W1 + e * C0 * C1;
    const float* W2e = W2 + e * C1 * C2;
    for (int d = t; d < IN0 * C0; d += TPB) sW0[d] = W0e[d];
    for (int d = t; d < C0 * C1;  d += TPB) sW1[d] = W1e[d];
    for (int d = t; d < C1 * C2;  d += TPB) sW2[d] = W2e[d];
    if (t < C0) sB0[t] = b0[e * C0 + t];
    if (t < C1) sB1[t] = b1[e * C1 + t];
    if (t < C2) sB2[t] = b2[e * C2 + t];
    __syncthreads();

    const int seg0 = (e << SEG_SHIFT) + local_base;
    int  local[PPT];
    bool valid[PPT];
    float h0[PPT][8];
    #pragma unroll
    for (int q = 0; q < PPT; q++) {
        local[q] = local_base + t + q * TPB;
        valid[q] = local[q] < cnt;
        const int slot = seg0 + t + q * TPB;
        if (valid[q]) {
            float4 a = g_xb[2 * slot];
            float4 b = g_xb[2 * slot + 1];
            h0[q][0]=a.x; h0[q][1]=a.y; h0[q][2]=a.z; h0[q][3]=a.w;
            h0[q][4]=b.x; h0[q][5]=b.y; h0[q][6]=b.z;
        } else {
            #pragma unroll
            for (int i = 0; i < 7; i++) h0[q][i] = 0.f;
        }
    }

    // ---- layer 0: 7 -> 16 ----
    float2 a0[PPT][C0 / 2];
    #pragma unroll
    for (int o = 0; o < C0 / 2; o++) {
        float2 bv = ((const float2*)sB0)[o];
        a0[0][o] = bv; a0[1][o] = bv;
    }
    #pragma unroll
    for (int i = 0; i < IN0; i++) {
        float2 hA = make_float2(h0[0][i], h0[0][i]);
        float2 hB = make_float2(h0[1][i], h0[1][i]);
        #pragma unroll
        for (int q4 = 0; q4 < C0 / 4; q4++) {
            float4 w = *(const float4*)&sW0[i * C0 + 4 * q4];
            float2 w01 = make_float2(w.x, w.y), w23 = make_float2(w.z, w.w);
            a0[0][2*q4]   = ffma2(hA, w01, a0[0][2*q4]);
            a0[0][2*q4+1] = ffma2(hA, w23, a0[0][2*q4+1]);
            a0[1][2*q4]   = ffma2(hB, w01, a0[1][2*q4]);
            a0[1][2*q4+1] = ffma2(hB, w23, a0[1][2*q4+1]);
        }
    }
    float h1[PPT][C0];
    #pragma unroll
    for (int q = 0; q < PPT; q++)
        #pragma unroll
        for (int o = 0; o < C0 / 2; o++) {
            h1[q][2*o]   = lrelu(a0[q][o].x);
            h1[q][2*o+1] = lrelu(a0[q][o].y);
        }

    // ---- layer 1: 16 -> 32 ----
    float2 a1[PPT][C1 / 2];
    #pragma unroll
    for (int o = 0; o < C1 / 2; o++) {
        float2 bv = ((const float2*)sB1)[o];
        a1[0][o] = bv; a1[1][o] = bv;
    }
    #pragma unroll
    for (int i = 0; i < C0; i++) {
        float2 hA = make_float2(h1[0][i], h1[0][i]);
        float2 hB = make_float2(h1[1][i], h1[1][i]);
        #pragma unroll
        for (int q4 = 0; q4 < C1 / 4; q4++) {
            float4 w = *(const float4*)&sW1[i * C1 + 4 * q4];
            float2 w01 = make_float2(w.x, w.y), w23 = make_float2(w.z, w.w);
            a1[0][2*q4]   = ffma2(hA, w01, a1[0][2*q4]);
            a1[0][2*q4+1] = ffma2(hA, w23, a1[0][2*q4+1]);
            a1[1][2*q4]   = ffma2(hB, w01, a1[1][2*q4]);
            a1[1][2*q4+1] = ffma2(hB, w23, a1[1][2*q4+1]);
        }
    }
    float h2[PPT][C1];
    #pragma unroll
    for (int q = 0; q < PPT; q++)
        #pragma unroll
        for (int o = 0; o < C1 / 2; o++) {
            h2[q][2*o]   = lrelu(a1[q][o].x);
            h2[q][2*o+1] = lrelu(a1[q][o].y);
        }

    // ---- layer 2: 32 -> 16 ----
    float2 a2[PPT][C2 / 2];
    #pragma unroll
    for (int o = 0; o < C2 / 2; o++) {
        float2 bv = ((const float2*)sB2)[o];
        a2[0][o] = bv; a2[1][o] = bv;
    }
    #pragma unroll
    for (int i = 0; i < C1; i++) {
        float2 hA = make_float2(h2[0][i], h2[0][i]);
        float2 hB = make_float2(h2[1][i], h2[1][i]);
        #pragma unroll
        for (int q4 = 0; q4 < C2 / 4; q4++) {
            float4 w = *(const float4*)&sW2[i * C2 + 4 * q4];
            float2 w01 = make_float2(w.x, w.y), w23 = make_float2(w.z, w.w);
            a2[0][2*q4]   = ffma2(hA, w01, a2[0][2*q4]);
            a2[0][2*q4+1] = ffma2(hA, w23, a2[0][2*q4+1]);
            a2[1][2*q4]   = ffma2(hB, w01, a2[1][2*q4]);
            a2[1][2*q4+1] = ffma2(hB, w23, a2[1][2*q4+1]);
        }
    }

    #pragma unroll
    for (int q = 0; q < PPT; q++) {
        if (valid[q]) {
            const int p = g_perm[seg0 + t + q * TPB];
            float ho[C2];
            #pragma unroll
            for (int o = 0; o < C2 / 2; o++) {
                ho[2*o]   = lrelu(a2[q][o].x);
                ho[2*o+1] = lrelu(a2[q][o].y);
            }
            float4* op = reinterpret_cast<float4*>(out + (size_t)p * C2);
            op[0] = make_float4(ho[0],  ho[1],  ho[2],  ho[3]);
            op[1] = make_float4(ho[4],  ho[5],  ho[6],  ho[7]);
            op[2] = make_float4(ho[8],  ho[9],  ho[10], ho[11]);
            op[3] = make_float4(ho[12], ho[13], ho[14], ho[15]);
        }
    }
}

extern "C" void kernel_launch(void* const* d_in, const int* in_sizes, int n_in,
                              void* d_out, int out_size)
{
    const float* x   = (const float*)d_in[0];
    const int*   idx = (const int*)  d_in[1];
    const float* W0  = (const float*)d_in[2];
    const float* b0  = (const float*)d_in[3];
    const float* W1  = (const float*)d_in[4];
    const float* b1  = (const float*)d_in[5];
    const float* W2  = (const float*)d_in[6];
    const float* b2  = (const float*)d_in[7];
    float* out = (float*)d_out;

    const int n = in_sizes[1];

    k_init<<<1, 32>>>();
    k_scatter<<<(n + TPB - 1) / TPB, TPB>>>(idx, x, n);
    k_main<<<GRID_MAIN, TPB>>>(W0, b0, W1, b1, W2, b2, out);
}